// round 11
// baseline (speedup 1.0000x reference)
#include <cuda_runtime.h>
#include <cstdint>

#define NN 50000
#define EE 600000
#define PP 100000
#define FD 128

// ---- device scratch ----
__device__ float g_agg[NN * FD];     // MEAN aggregate
__device__ float g_h1[NN * FD];
__device__ float g_h2[NN * FD];
__device__ int   g_cnt[NN];          // restored to 0 by fill_kernel each run
__device__ int   g_rowstart[NN + 1];
__device__ int   g_csr[EE];

typedef unsigned long long u64;

__device__ __forceinline__ void ffma2(u64& d, u64 a, u64 b) {
    asm("fma.rn.f32x2 %0, %1, %2, %0;" : "+l"(d) : "l"(a), "l"(b));
}
__device__ __forceinline__ void unpack2(float& lo, float& hi, u64 v) {
    asm("mov.b64 {%0, %1}, %2;" : "=f"(lo), "=f"(hi) : "l"(v));
}
__device__ __forceinline__ u64 pack_dup(float a) {
    u64 r;
    asm("mov.b64 %0, {%1, %1};" : "=l"(r) : "f"(a));
    return r;
}

// ============================================================================
// CSR build: count -> scan -> fill (fill restores g_cnt to zero)
// ============================================================================
__global__ void count_kernel(const int* __restrict__ dst)
{
    int e = blockIdx.x * blockDim.x + threadIdx.x;
    if (e < EE) atomicAdd(&g_cnt[dst[e]], 1);
}

__global__ void __launch_bounds__(1024, 1) scan_kernel()
{
    __shared__ int wsum[32];
    __shared__ int carry;
    int tid = threadIdx.x, lane = tid & 31, w = tid >> 5;
    if (tid == 0) carry = 0;
    __syncthreads();
    for (int base = 0; base < NN; base += 1024) {
        int i = base + tid;
        int v = (i < NN) ? g_cnt[i] : 0;
        int s = v;
#pragma unroll
        for (int off = 1; off < 32; off <<= 1) {
            int t = __shfl_up_sync(0xffffffffu, s, off);
            if (lane >= off) s += t;
        }
        if (lane == 31) wsum[w] = s;
        __syncthreads();
        if (w == 0) {
            int ws = wsum[lane];
#pragma unroll
            for (int off = 1; off < 32; off <<= 1) {
                int t = __shfl_up_sync(0xffffffffu, ws, off);
                if (lane >= off) ws += t;
            }
            wsum[lane] = ws;
        }
        __syncthreads();
        int prev = (w > 0) ? wsum[w - 1] : 0;
        int incl = carry + prev + s;
        if (i < NN) g_rowstart[i + 1] = incl;
        int chunk_total = wsum[31];
        __syncthreads();
        if (tid == 0) carry += chunk_total;
        __syncthreads();
    }
    if (threadIdx.x == 0) g_rowstart[0] = 0;
}

__global__ void fill_kernel(const int* __restrict__ src,
                            const int* __restrict__ dst)
{
    int e = blockIdx.x * blockDim.x + threadIdx.x;
    if (e >= EE) return;
    int d = dst[e];
    int p = atomicAdd(&g_cnt[d], -1) - 1;     // leaves g_cnt[d] at 0 when done
    g_csr[g_rowstart[d] + p] = src[e];
}

// ============================================================================
// Aggregate (proven form)
// ============================================================================
__global__ void aggregate_kernel(const float* __restrict__ h)
{
    int gw   = (blockIdx.x * blockDim.x + threadIdx.x) >> 5;
    int lane = threadIdx.x & 31;
    if (gw >= NN) return;
    int beg = g_rowstart[gw], end = g_rowstart[gw + 1];
    const float* hp = h + lane * 4;
    float4 acc = make_float4(0.f, 0.f, 0.f, 0.f);
    int e = beg;
    for (; e + 1 < end; e += 2) {
        int s0 = g_csr[e], s1 = g_csr[e + 1];
        float4 v0 = *(const float4*)(hp + s0 * FD);
        float4 v1 = *(const float4*)(hp + s1 * FD);
        acc.x += v0.x + v1.x; acc.y += v0.y + v1.y;
        acc.z += v0.z + v1.z; acc.w += v0.w + v1.w;
    }
    if (e < end) {
        int s0 = g_csr[e];
        float4 v0 = *(const float4*)(hp + s0 * FD);
        acc.x += v0.x; acc.y += v0.y; acc.z += v0.z; acc.w += v0.w;
    }
    float rd = 1.0f / fmaxf((float)(end - beg), 1.0f);
    acc.x *= rd; acc.y *= rd; acc.z *= rd; acc.w *= rd;
    *(float4*)(g_agg + gw * FD + lane * 4) = acc;
}

// ============================================================================
// Half-K SAGE linear with DUPLICATED activation staging (mov-free inner loop).
// Weight layout/access identical to proven R8 form; only activations change.
// ADD=false: out = src @ W + b ; ADD=true: out += src @ W (then opt RELU)
// ============================================================================
template <bool ADD, bool RELU>
__global__ void __launch_bounds__(512, 1)
sage_half_kernel(const float* __restrict__ src,
                 const float* __restrict__ W,
                 const float* __restrict__ b,
                 float* __restrict__ out,
                 int rpb)
{
    extern __shared__ float sm[];
    float* smW  = sm;                        // [128][128] fp32 weights (64KB)
    u64*   dstg = (u64*)(sm + 128 * 128);    // [16 warps][8 rows][128] u64 (128KB)

    int tid  = threadIdx.x;
    int lane = tid & 31;
    int warp = tid >> 5;

    for (int i = tid; i < (128 * 128) / 4; i += blockDim.x)
        ((float4*)smW)[i] = ((const float4*)W)[i];
    __syncthreads();

    int bstart = blockIdx.x * rpb;
    int bend   = min(bstart + rpb, NN);

    float4 bias = make_float4(0.f, 0.f, 0.f, 0.f);
    if (!ADD) bias = *(const float4*)(b + lane * 4);
    u64* myStage = dstg + warp * (8 * 128);

    for (int base = bstart + warp * 8; base < bend; base += 128) {

        // ---- stage 8 rows, values pre-duplicated into (x,x) u64 ----
#pragma unroll
        for (int r = 0; r < 8; r++) {
            int row = base + r;
            float4 v = make_float4(0.f, 0.f, 0.f, 0.f);
            if (row < bend)
                v = *(const float4*)(src + row * FD + lane * 4);
            ulonglong2 d0, d1;
            d0.x = pack_dup(v.x); d0.y = pack_dup(v.y);
            d1.x = pack_dup(v.z); d1.y = pack_dup(v.w);
            *(ulonglong2*)(myStage + r * 128 + lane * 4)     = d0;
            *(ulonglong2*)(myStage + r * 128 + lane * 4 + 2) = d1;
        }
        __syncwarp();

        u64 acc[8][2];
#pragma unroll
        for (int r = 0; r < 8; r++) { acc[r][0] = 0ull; acc[r][1] = 0ull; }

#pragma unroll 1
        for (int k = 0; k < 128; k += 4) {
            ulonglong2 w0 = *(const ulonglong2*)(smW + (k + 0) * 128 + lane * 4);
            ulonglong2 w1 = *(const ulonglong2*)(smW + (k + 1) * 128 + lane * 4);
            ulonglong2 w2 = *(const ulonglong2*)(smW + (k + 2) * 128 + lane * 4);
            ulonglong2 w3 = *(const ulonglong2*)(smW + (k + 3) * 128 + lane * 4);
#pragma unroll
            for (int r = 0; r < 8; r++) {
                ulonglong2 aA = *(const ulonglong2*)(myStage + r * 128 + k);
                ulonglong2 aB = *(const ulonglong2*)(myStage + r * 128 + k + 2);
                ffma2(acc[r][0], aA.x, w0.x);
                ffma2(acc[r][1], aA.x, w0.y);
                ffma2(acc[r][0], aA.y, w1.x);
                ffma2(acc[r][1], aA.y, w1.y);
                ffma2(acc[r][0], aB.x, w2.x);
                ffma2(acc[r][1], aB.x, w2.y);
                ffma2(acc[r][0], aB.y, w3.x);
                ffma2(acc[r][1], aB.y, w3.y);
            }
        }
        __syncwarp();

#pragma unroll
        for (int r = 0; r < 8; r++) {
            int row = base + r;
            if (row < bend) {
                float4 o;
                unpack2(o.x, o.y, acc[r][0]);
                unpack2(o.z, o.w, acc[r][1]);
                float4* op = (float4*)(out + row * FD + lane * 4);
                if (ADD) {
                    float4 prev = *op;
                    o.x += prev.x; o.y += prev.y; o.z += prev.z; o.w += prev.w;
                } else {
                    o.x += bias.x; o.y += bias.y; o.z += bias.z; o.w += bias.w;
                }
                if (RELU) {
                    o.x = fmaxf(o.x, 0.f); o.y = fmaxf(o.y, 0.f);
                    o.z = fmaxf(o.z, 0.f); o.w = fmaxf(o.w, 0.f);
                }
                *op = o;
            }
        }
    }
}

// ============================================================================
// Fused decoder (R10 form, frozen)
// ============================================================================
__global__ void __launch_bounds__(512, 1)
decoder_kernel(const float* __restrict__ h,
               const int* __restrict__ ps, const int* __restrict__ pd,
               const int* __restrict__ ns, const int* __restrict__ nd,
               const float* __restrict__ Wd1, const float* __restrict__ bd1,
               const float* __restrict__ Wd2, const float* __restrict__ bd2,
               const float* __restrict__ Wd3, const float* __restrict__ bd3,
               float* __restrict__ out,
               int rpb)
{
    extern __shared__ float sm[];
    float* smW1  = sm;
    float* smW2  = sm + 128 * 128;
    float* stage = sm + 2 * 128 * 128;

    int tid  = threadIdx.x;
    int lane = tid & 31;
    int warp = tid >> 5;

    for (int i = tid; i < (128 * 128) / 4; i += blockDim.x) {
        ((float4*)smW1)[i] = ((const float4*)Wd1)[i];
        ((float4*)smW2)[i] = ((const float4*)Wd2)[i];
    }
    __syncthreads();

    float4 b1v = *(const float4*)(bd1 + lane * 4);
    float4 b2v = *(const float4*)(bd2 + lane * 4);
    float4 w3v = *(const float4*)(Wd3 + lane * 4);
    float  b3  = bd3[0];

    float* myStage = stage + warp * (8 * 128);
    const int total = 2 * PP;

    int bstart = blockIdx.x * rpb;
    int bend   = min(bstart + rpb, total);

    for (int base = bstart + warp * 8; base < bend; base += 128) {
#pragma unroll
        for (int r = 0; r < 8; r++) {
            int p = base + r;
            float4 z = make_float4(0.f, 0.f, 0.f, 0.f);
            if (p < bend) {
                int s, d;
                if (p < PP) { s = ps[p]; d = pd[p]; }
                else        { s = ns[p - PP]; d = nd[p - PP]; }
                float4 a = *(const float4*)(h + s * FD + lane * 4);
                float4 c = *(const float4*)(h + d * FD + lane * 4);
                z.x = a.x * c.x; z.y = a.y * c.y;
                z.z = a.z * c.z; z.w = a.w * c.w;
            }
            *(float4*)(myStage + r * 128 + lane * 4) = z;
        }
        __syncwarp();

        u64 acc[8][2];

#pragma unroll
        for (int r = 0; r < 8; r++) { acc[r][0] = 0ull; acc[r][1] = 0ull; }
#pragma unroll 1
        for (int k = 0; k < 128; k += 4) {
            float4 zq[8];
#pragma unroll
            for (int r = 0; r < 8; r++)
                zq[r] = *(const float4*)(myStage + r * 128 + k);
#pragma unroll
            for (int kk = 0; kk < 4; kk++) {
                ulonglong2 w = *(const ulonglong2*)(smW1 + (k + kk) * 128 + lane * 4);
#pragma unroll
                for (int r = 0; r < 8; r++) {
                    float zs = (kk == 0) ? zq[r].x : (kk == 1) ? zq[r].y
                             : (kk == 2) ? zq[r].z : zq[r].w;
                    u64 zz = pack_dup(zs);
                    ffma2(acc[r][0], zz, w.x);
                    ffma2(acc[r][1], zz, w.y);
                }
            }
        }
        __syncwarp();

#pragma unroll
        for (int r = 0; r < 8; r++) {
            float lo0, hi0, lo1, hi1;
            unpack2(lo0, hi0, acc[r][0]);
            unpack2(lo1, hi1, acc[r][1]);
            float4 tq;
            tq.x = fmaxf(lo0 + b1v.x, 0.f);
            tq.y = fmaxf(hi0 + b1v.y, 0.f);
            tq.z = fmaxf(lo1 + b1v.z, 0.f);
            tq.w = fmaxf(hi1 + b1v.w, 0.f);
            *(float4*)(myStage + r * 128 + lane * 4) = tq;
        }
        __syncwarp();

#pragma unroll
        for (int r = 0; r < 8; r++) { acc[r][0] = 0ull; acc[r][1] = 0ull; }
#pragma unroll 1
        for (int k = 0; k < 128; k += 4) {
            float4 zq[8];
#pragma unroll
            for (int r = 0; r < 8; r++)
                zq[r] = *(const float4*)(myStage + r * 128 + k);
#pragma unroll
            for (int kk = 0; kk < 4; kk++) {
                ulonglong2 w = *(const ulonglong2*)(smW2 + (k + kk) * 128 + lane * 4);
#pragma unroll
                for (int r = 0; r < 8; r++) {
                    float zs = (kk == 0) ? zq[r].x : (kk == 1) ? zq[r].y
                             : (kk == 2) ? zq[r].z : zq[r].w;
                    u64 zz = pack_dup(zs);
                    ffma2(acc[r][0], zz, w.x);
                    ffma2(acc[r][1], zz, w.y);
                }
            }
        }

#pragma unroll
        for (int r = 0; r < 8; r++) {
            float t0, t1, t2, t3;
            unpack2(t0, t1, acc[r][0]);
            unpack2(t2, t3, acc[r][1]);
            t0 = fmaxf(t0 + b2v.x, 0.f);
            t1 = fmaxf(t1 + b2v.y, 0.f);
            t2 = fmaxf(t2 + b2v.z, 0.f);
            t3 = fmaxf(t3 + b2v.w, 0.f);
            float partial = t0 * w3v.x + t1 * w3v.y + t2 * w3v.z + t3 * w3v.w;
#pragma unroll
            for (int off = 16; off > 0; off >>= 1)
                partial += __shfl_xor_sync(0xffffffffu, partial, off);
            int p = base + r;
            if (lane == 0 && p < bend) out[p] = partial + b3;
        }
        __syncwarp();
    }
}

// ============================================================================
// launch — two-stream fork/join (R10 structure)
// ============================================================================
extern "C" void kernel_launch(void* const* d_in, const int* in_sizes, int n_in,
                              void* d_out, int out_size)
{
    const float* x    = (const float*)d_in[0];
    const int*   esrc = (const int*)  d_in[1];
    const int*   edst = (const int*)  d_in[2];
    const int*   ps   = (const int*)  d_in[3];
    const int*   pd   = (const int*)  d_in[4];
    const int*   ns   = (const int*)  d_in[5];
    const int*   nd   = (const int*)  d_in[6];
    const float* Ws1  = (const float*)d_in[7];
    const float* Wn1  = (const float*)d_in[8];
    const float* b1   = (const float*)d_in[9];
    const float* Ws2  = (const float*)d_in[10];
    const float* Wn2  = (const float*)d_in[11];
    const float* b2   = (const float*)d_in[12];
    const float* Wd1  = (const float*)d_in[13];
    const float* bd1  = (const float*)d_in[14];
    const float* Wd2  = (const float*)d_in[15];
    const float* bd2  = (const float*)d_in[16];
    const float* Wd3  = (const float*)d_in[17];
    const float* bd3  = (const float*)d_in[18];
    float* out = (float*)d_out;

    void *aggPtr, *h1Ptr, *h2Ptr;
    cudaGetSymbolAddress(&aggPtr, g_agg);
    cudaGetSymbolAddress(&h1Ptr,  g_h1);
    cudaGetSymbolAddress(&h2Ptr,  g_h2);
    float* h1 = (float*)h1Ptr;
    float* h2 = (float*)h2Ptr;
    float* agg = (float*)aggPtr;

    int nsm = 148;
    cudaDeviceGetAttribute(&nsm, cudaDevAttrMultiProcessorCount, 0);

    int rpb_sage = (((NN + nsm - 1) / nsm) + 7) & ~7;
    int rpb_dec  = (((2 * PP + nsm - 1) / nsm) + 7) & ~7;

    const int HALF_SMEM = 128 * 128 * 4 + 16 * 8 * 128 * 8;       // 196608 B
    const int DEC_SMEM  = 2 * 128 * 128 * 4 + 16 * 8 * 128 * 4;   // 196608 B
    cudaFuncSetAttribute(sage_half_kernel<false, false>,
                         cudaFuncAttributeMaxDynamicSharedMemorySize, HALF_SMEM);
    cudaFuncSetAttribute(sage_half_kernel<true, true>,
                         cudaFuncAttributeMaxDynamicSharedMemorySize, HALF_SMEM);
    cudaFuncSetAttribute(sage_half_kernel<true, false>,
                         cudaFuncAttributeMaxDynamicSharedMemorySize, HALF_SMEM);
    cudaFuncSetAttribute(decoder_kernel,
                         cudaFuncAttributeMaxDynamicSharedMemorySize, DEC_SMEM);

    static cudaStream_t sB = nullptr;
    static cudaEvent_t evFork = nullptr, evAgg1 = nullptr,
                       evH1 = nullptr, evAgg2 = nullptr;
    if (sB == nullptr) {
        cudaStreamCreateWithFlags(&sB, cudaStreamNonBlocking);
        cudaEventCreateWithFlags(&evFork, cudaEventDisableTiming);
        cudaEventCreateWithFlags(&evAgg1, cudaEventDisableTiming);
        cudaEventCreateWithFlags(&evH1,   cudaEventDisableTiming);
        cudaEventCreateWithFlags(&evAgg2, cudaEventDisableTiming);
    }

    int ablocks = (NN * 32 + 255) / 256;

    // ---- fork ----
    cudaEventRecord(evFork, 0);
    cudaStreamWaitEvent(sB, evFork, 0);

    // streamB: CSR build + aggregate layer 1
    count_kernel<<<(EE + 255) / 256, 256, 0, sB>>>(edst);
    scan_kernel<<<1, 1024, 0, sB>>>();
    fill_kernel<<<(EE + 255) / 256, 256, 0, sB>>>(esrc, edst);
    aggregate_kernel<<<ablocks, 256, 0, sB>>>(x);
    cudaEventRecord(evAgg1, sB);

    // streamA: self half of layer 1 (concurrent with CSR+agg1)
    sage_half_kernel<false, false><<<nsm, 512, HALF_SMEM>>>(x, Ws1, b1, h1,
                                                            rpb_sage);
    cudaStreamWaitEvent(0, evAgg1, 0);
    sage_half_kernel<true, true><<<nsm, 512, HALF_SMEM>>>(agg, Wn1, b1, h1,
                                                          rpb_sage);
    cudaEventRecord(evH1, 0);

    // streamB: aggregate layer 2 (concurrent with sage2_self)
    cudaStreamWaitEvent(sB, evH1, 0);
    aggregate_kernel<<<ablocks, 256, 0, sB>>>(h1);
    cudaEventRecord(evAgg2, sB);

    // streamA: self half of layer 2
    sage_half_kernel<false, false><<<nsm, 512, HALF_SMEM>>>(h1, Ws2, b2, h2,
                                                            rpb_sage);
    cudaStreamWaitEvent(0, evAgg2, 0);
    sage_half_kernel<true, false><<<nsm, 512, HALF_SMEM>>>(agg, Wn2, b2, h2,
                                                           rpb_sage);

    // decoder
    decoder_kernel<<<nsm, 512, DEC_SMEM>>>(h2, ps, pd, ns, nd,
                                           Wd1, bd1, Wd2, bd2, Wd3, bd3, out,
                                           rpb_dec);
}

// round 12
// speedup vs baseline: 1.3301x; 1.3301x over previous
#include <cuda_runtime.h>
#include <cuda_bf16.h>
#include <cstdint>

#define NN 50000
#define EE 600000
#define PP 100000
#define FD 128

// ---- device scratch ----
__device__ float g_agg[NN * FD];
__device__ float g_h1[NN * FD];
__device__ float g_h2[NN * FD];
__device__ int   g_cnt[NN];          // restored to 0 by fill_kernel each run
__device__ int   g_rowstart[NN + 1];
__device__ int   g_csr[EE];

typedef unsigned long long u64;
typedef unsigned int u32;

__device__ __forceinline__ void ffma2(u64& d, u64 a, u64 b) {
    asm("fma.rn.f32x2 %0, %1, %2, %0;" : "+l"(d) : "l"(a), "l"(b));
}
__device__ __forceinline__ void unpack2(float& lo, float& hi, u64 v) {
    asm("mov.b64 {%0, %1}, %2;" : "=f"(lo), "=f"(hi) : "l"(v));
}
__device__ __forceinline__ u64 pack_dup(float a) {
    u64 r;
    asm("mov.b64 %0, {%1, %1};" : "=l"(r) : "f"(a));
    return r;
}

// bf16 split helpers
__device__ __forceinline__ void bf16_split(float x, unsigned short& h, unsigned short& l) {
    __nv_bfloat16 bh = __float2bfloat16(x);
    float r = x - __bfloat162float(bh);
    __nv_bfloat16 bl = __float2bfloat16(r);
    h = __bfloat16_as_ushort(bh);
    l = __bfloat16_as_ushort(bl);
}
__device__ __forceinline__ u32 pack16(unsigned short lo, unsigned short hi) {
    return (u32)lo | ((u32)hi << 16);
}

// m16n8k16 bf16 MMA, f32 accum
__device__ __forceinline__ void mma16816(float& c0, float& c1, float& c2, float& c3,
                                         u32 a0, u32 a1, u32 a2, u32 a3,
                                         u32 b0, u32 b1) {
    asm volatile(
        "mma.sync.aligned.m16n8k16.row.col.f32.bf16.bf16.f32 "
        "{%0,%1,%2,%3}, {%4,%5,%6,%7}, {%8,%9}, {%0,%1,%2,%3};"
        : "+f"(c0), "+f"(c1), "+f"(c2), "+f"(c3)
        : "r"(a0), "r"(a1), "r"(a2), "r"(a3), "r"(b0), "r"(b1));
}

// ============================================================================
// CSR build (R10, proven)
// ============================================================================
__global__ void count_kernel(const int* __restrict__ dst)
{
    int e = blockIdx.x * blockDim.x + threadIdx.x;
    if (e < EE) atomicAdd(&g_cnt[dst[e]], 1);
}

__global__ void __launch_bounds__(1024, 1) scan_kernel()
{
    __shared__ int wsum[32];
    __shared__ int carry;
    int tid = threadIdx.x, lane = tid & 31, w = tid >> 5;
    if (tid == 0) carry = 0;
    __syncthreads();
    for (int base = 0; base < NN; base += 1024) {
        int i = base + tid;
        int v = (i < NN) ? g_cnt[i] : 0;
        int s = v;
#pragma unroll
        for (int off = 1; off < 32; off <<= 1) {
            int t = __shfl_up_sync(0xffffffffu, s, off);
            if (lane >= off) s += t;
        }
        if (lane == 31) wsum[w] = s;
        __syncthreads();
        if (w == 0) {
            int ws = wsum[lane];
#pragma unroll
            for (int off = 1; off < 32; off <<= 1) {
                int t = __shfl_up_sync(0xffffffffu, ws, off);
                if (lane >= off) ws += t;
            }
            wsum[lane] = ws;
        }
        __syncthreads();
        int prev = (w > 0) ? wsum[w - 1] : 0;
        int incl = carry + prev + s;
        if (i < NN) g_rowstart[i + 1] = incl;
        int chunk_total = wsum[31];
        __syncthreads();
        if (tid == 0) carry += chunk_total;
        __syncthreads();
    }
    if (threadIdx.x == 0) g_rowstart[0] = 0;
}

__global__ void fill_kernel(const int* __restrict__ src,
                            const int* __restrict__ dst)
{
    int e = blockIdx.x * blockDim.x + threadIdx.x;
    if (e >= EE) return;
    int d = dst[e];
    int p = atomicAdd(&g_cnt[d], -1) - 1;
    g_csr[g_rowstart[d] + p] = src[e];
}

// ============================================================================
// Aggregate (R10, proven)
// ============================================================================
__global__ void aggregate_kernel(const float* __restrict__ h)
{
    int gw   = (blockIdx.x * blockDim.x + threadIdx.x) >> 5;
    int lane = threadIdx.x & 31;
    if (gw >= NN) return;
    int beg = g_rowstart[gw], end = g_rowstart[gw + 1];
    const float* hp = h + lane * 4;
    float4 acc = make_float4(0.f, 0.f, 0.f, 0.f);
    int e = beg;
    for (; e + 1 < end; e += 2) {
        int s0 = g_csr[e], s1 = g_csr[e + 1];
        float4 v0 = *(const float4*)(hp + s0 * FD);
        float4 v1 = *(const float4*)(hp + s1 * FD);
        acc.x += v0.x + v1.x; acc.y += v0.y + v1.y;
        acc.z += v0.z + v1.z; acc.w += v0.w + v1.w;
    }
    if (e < end) {
        int s0 = g_csr[e];
        float4 v0 = *(const float4*)(hp + s0 * FD);
        acc.x += v0.x; acc.y += v0.y; acc.z += v0.z; acc.w += v0.w;
    }
    float rd = 1.0f / fmaxf((float)(end - beg), 1.0f);
    acc.x *= rd; acc.y *= rd; acc.z *= rd; acc.w *= rd;
    *(float4*)(g_agg + gw * FD + lane * 4) = acc;
}

// ============================================================================
// Half-K SAGE linear (R10 FFMA2 form, FROZEN)
// ============================================================================
template <bool ADD, bool RELU>
__global__ void __launch_bounds__(512, 1)
sage_half_kernel(const float* __restrict__ src,
                 const float* __restrict__ W,
                 const float* __restrict__ b,
                 float* __restrict__ out,
                 int rpb)
{
    extern __shared__ float sm[];
    float* smW   = sm;                 // [128][128]
    float* stage = sm + 128 * 128;     // [16][8][128]

    int tid  = threadIdx.x;
    int lane = tid & 31;
    int warp = tid >> 5;

    for (int i = tid; i < (128 * 128) / 4; i += blockDim.x)
        ((float4*)smW)[i] = ((const float4*)W)[i];
    __syncthreads();

    int bstart = blockIdx.x * rpb;
    int bend   = min(bstart + rpb, NN);

    float4 bias = make_float4(0.f, 0.f, 0.f, 0.f);
    if (!ADD) bias = *(const float4*)(b + lane * 4);
    float* myStage = stage + warp * (8 * 128);

    for (int base = bstart + warp * 8; base < bend; base += 128) {

#pragma unroll
        for (int r = 0; r < 8; r++) {
            int row = base + r;
            float4 v = make_float4(0.f, 0.f, 0.f, 0.f);
            if (row < bend)
                v = *(const float4*)(src + row * FD + lane * 4);
            *(float4*)(myStage + r * 128 + lane * 4) = v;
        }
        __syncwarp();

        u64 acc[8][2];
#pragma unroll
        for (int r = 0; r < 8; r++) { acc[r][0] = 0ull; acc[r][1] = 0ull; }

#pragma unroll 1
        for (int k = 0; k < 128; k += 4) {
            float4 xq[8];
#pragma unroll
            for (int r = 0; r < 8; r++)
                xq[r] = *(const float4*)(myStage + r * 128 + k);
#pragma unroll
            for (int kk = 0; kk < 4; kk++) {
                ulonglong2 w = *(const ulonglong2*)(smW + (k + kk) * 128 + lane * 4);
#pragma unroll
                for (int r = 0; r < 8; r++) {
                    float xs = (kk == 0) ? xq[r].x : (kk == 1) ? xq[r].y
                             : (kk == 2) ? xq[r].z : xq[r].w;
                    u64 xx = pack_dup(xs);
                    ffma2(acc[r][0], xx, w.x);
                    ffma2(acc[r][1], xx, w.y);
                }
            }
        }
        __syncwarp();

#pragma unroll
        for (int r = 0; r < 8; r++) {
            int row = base + r;
            if (row < bend) {
                float4 o;
                unpack2(o.x, o.y, acc[r][0]);
                unpack2(o.z, o.w, acc[r][1]);
                float4* op = (float4*)(out + row * FD + lane * 4);
                if (ADD) {
                    float4 prev = *op;
                    o.x += prev.x; o.y += prev.y; o.z += prev.z; o.w += prev.w;
                } else {
                    o.x += bias.x; o.y += bias.y; o.z += bias.z; o.w += bias.w;
                }
                if (RELU) {
                    o.x = fmaxf(o.x, 0.f); o.y = fmaxf(o.y, 0.f);
                    o.z = fmaxf(o.z, 0.f); o.w = fmaxf(o.w, 0.f);
                }
                *op = o;
            }
        }
    }
}

// ============================================================================
// Decoder via mma.sync m16n8k16 bf16 3-term split.
// Block: 16 warps = 4 row-groups (16 rows) x 4 col-groups (32 cols).
// Tile: 64 pair-rows x 128 cols. K=128 per GEMV.
// smem (u32 units): W1h/W1l/W2h/W2l [64][136]; zh/zl [64][68];
//                   b1s/b2s/w3s [128]f32; scratch [64][4]f32.
// ============================================================================
#define PW 136
#define PZ 68
#define OFF_W1H 0
#define OFF_W1L (OFF_W1H + 64 * PW)
#define OFF_W2H (OFF_W1L + 64 * PW)
#define OFF_W2L (OFF_W2H + 64 * PW)
#define OFF_ZH  (OFF_W2L + 64 * PW)
#define OFF_ZL  (OFF_ZH + 64 * PZ)
#define OFF_B1  (OFF_ZL + 64 * PZ)
#define OFF_B2  (OFF_B1 + 128)
#define OFF_W3  (OFF_B2 + 128)
#define OFF_RED (OFF_W3 + 128)
#define DEC_U32 (OFF_RED + 64 * 4)

__global__ void __launch_bounds__(512, 1)
decoder_kernel(const float* __restrict__ h,
               const int* __restrict__ ps, const int* __restrict__ pd,
               const int* __restrict__ ns, const int* __restrict__ nd,
               const float* __restrict__ Wd1, const float* __restrict__ bd1,
               const float* __restrict__ Wd2, const float* __restrict__ bd2,
               const float* __restrict__ Wd3, const float* __restrict__ bd3,
               float* __restrict__ out,
               int rpb)
{
    extern __shared__ u32 smu[];
    u32* W1h = smu + OFF_W1H;
    u32* W1l = smu + OFF_W1L;
    u32* W2h = smu + OFF_W2H;
    u32* W2l = smu + OFF_W2L;
    u32* zh  = smu + OFF_ZH;
    u32* zl  = smu + OFF_ZL;
    float* b1s = (float*)(smu + OFF_B1);
    float* b2s = (float*)(smu + OFF_B2);
    float* w3s = (float*)(smu + OFF_W3);
    float* red = (float*)(smu + OFF_RED);

    int tid  = threadIdx.x;
    int lane = tid & 31;
    int warp = tid >> 5;
    int g    = lane >> 2;      // group 0..7
    int tg   = lane & 3;       // thread-in-group 0..3
    int wr   = warp & 3;       // row-group: rows [wr*16, wr*16+16)
    int wc   = warp >> 2;      // col-group: cols [wc*32, wc*32+32)

    // ---- prologue: weights split to bf16 pairs (k-interleaved), biases ----
    for (int i = tid; i < 64 * 128; i += 512) {
        int t = i >> 7, c = i & 127;
        unsigned short h0, l0, h1, l1;
        float a0 = Wd1[(2 * t) * 128 + c], a1 = Wd1[(2 * t + 1) * 128 + c];
        bf16_split(a0, h0, l0); bf16_split(a1, h1, l1);
        W1h[t * PW + c] = pack16(h0, h1);
        W1l[t * PW + c] = pack16(l0, l1);
        float b0f = Wd2[(2 * t) * 128 + c], b1f = Wd2[(2 * t + 1) * 128 + c];
        bf16_split(b0f, h0, l0); bf16_split(b1f, h1, l1);
        W2h[t * PW + c] = pack16(h0, h1);
        W2l[t * PW + c] = pack16(l0, l1);
    }
    if (tid < 128) {
        b1s[tid] = bd1[tid];
        b2s[tid] = bd2[tid];
        w3s[tid] = Wd3[tid];
    }
    __syncthreads();

    const float b3 = bd3[0];
    const int total = 2 * PP;
    int bstart = blockIdx.x * rpb;
    int bend   = min(bstart + rpb, total);

    for (int tb = bstart; tb < bend; tb += 64) {

        // ---- stage z = h[s]*h[d], split to bf16 hi/lo pairs ----
        {
#pragma unroll
            for (int i = 0; i < 4; i++) {
                int rl = warp * 4 + i;          // 0..63
                int p  = tb + rl;
                float4 v = make_float4(0.f, 0.f, 0.f, 0.f);
                if (p < total) {
                    int s, d;
                    if (p < PP) { s = ps[p]; d = pd[p]; }
                    else        { s = ns[p - PP]; d = nd[p - PP]; }
                    float4 a = *(const float4*)(h + s * FD + lane * 4);
                    float4 c = *(const float4*)(h + d * FD + lane * 4);
                    v.x = a.x * c.x; v.y = a.y * c.y;
                    v.z = a.z * c.z; v.w = a.w * c.w;
                }
                unsigned short h0, l0, h1, l1, h2_, l2_, h3_, l3_;
                bf16_split(v.x, h0, l0); bf16_split(v.y, h1, l1);
                bf16_split(v.z, h2_, l2_); bf16_split(v.w, h3_, l3_);
                u32 base_ = rl * PZ + 2 * lane;
                *(uint2*)(zh + base_) = make_uint2(pack16(h0, h1), pack16(h2_, h3_));
                *(uint2*)(zl + base_) = make_uint2(pack16(l0, l1), pack16(l2_, l3_));
            }
        }
        __syncthreads();

        float acc[4][4];
        int rb = wr * 16;
        int cb = wc * 32;

        // ================= GEMV 1 =================
#pragma unroll
        for (int j = 0; j < 4; j++)
#pragma unroll
            for (int q = 0; q < 4; q++) acc[j][q] = 0.f;

#pragma unroll 1
        for (int ks = 0; ks < 8; ks++) {
            int ko = ks * 8;
            u32 ah0 = zh[(rb + g) * PZ + ko + tg];
            u32 ah1 = zh[(rb + 8 + g) * PZ + ko + tg];
            u32 ah2 = zh[(rb + g) * PZ + ko + 4 + tg];
            u32 ah3 = zh[(rb + 8 + g) * PZ + ko + 4 + tg];
            u32 al0 = zl[(rb + g) * PZ + ko + tg];
            u32 al1 = zl[(rb + 8 + g) * PZ + ko + tg];
            u32 al2 = zl[(rb + g) * PZ + ko + 4 + tg];
            u32 al3 = zl[(rb + 8 + g) * PZ + ko + 4 + tg];
#pragma unroll
            for (int j = 0; j < 4; j++) {
                int c0 = cb + j * 8 + g;
                u32 bh0 = W1h[(ko + tg) * PW + c0];
                u32 bh1 = W1h[(ko + 4 + tg) * PW + c0];
                u32 bl0 = W1l[(ko + tg) * PW + c0];
                u32 bl1 = W1l[(ko + 4 + tg) * PW + c0];
                mma16816(acc[j][0], acc[j][1], acc[j][2], acc[j][3],
                         ah0, ah1, ah2, ah3, bh0, bh1);
                mma16816(acc[j][0], acc[j][1], acc[j][2], acc[j][3],
                         ah0, ah1, ah2, ah3, bl0, bl1);
                mma16816(acc[j][0], acc[j][1], acc[j][2], acc[j][3],
                         al0, al1, al2, al3, bh0, bh1);
            }
        }
        __syncthreads();   // all reads of z done before t1 overwrite

        // ---- t1 = relu(acc + b1), restage as bf16 pairs ----
#pragma unroll
        for (int j = 0; j < 4; j++) {
            int col0 = cb + j * 8 + 2 * tg;
            float t0 = fmaxf(acc[j][0] + b1s[col0],     0.f);
            float t1 = fmaxf(acc[j][1] + b1s[col0 + 1], 0.f);
            float t2 = fmaxf(acc[j][2] + b1s[col0],     0.f);
            float t3 = fmaxf(acc[j][3] + b1s[col0 + 1], 0.f);
            unsigned short h0, l0, h1, l1;
            int t2i = col0 >> 1;   // pair index for GEMV2 (k = col)
            bf16_split(t0, h0, l0); bf16_split(t1, h1, l1);
            zh[(rb + g) * PZ + t2i] = pack16(h0, h1);
            zl[(rb + g) * PZ + t2i] = pack16(l0, l1);
            bf16_split(t2, h0, l0); bf16_split(t3, h1, l1);
            zh[(rb + 8 + g) * PZ + t2i] = pack16(h0, h1);
            zl[(rb + 8 + g) * PZ + t2i] = pack16(l0, l1);
        }
        __syncthreads();

        // ================= GEMV 2 =================
#pragma unroll
        for (int j = 0; j < 4; j++)
#pragma unroll
            for (int q = 0; q < 4; q++) acc[j][q] = 0.f;

#pragma unroll 1
        for (int ks = 0; ks < 8; ks++) {
            int ko = ks * 8;
            u32 ah0 = zh[(rb + g) * PZ + ko + tg];
            u32 ah1 = zh[(rb + 8 + g) * PZ + ko + tg];
            u32 ah2 = zh[(rb + g) * PZ + ko + 4 + tg];
            u32 ah3 = zh[(rb + 8 + g) * PZ + ko + 4 + tg];
            u32 al0 = zl[(rb + g) * PZ + ko + tg];
            u32 al1 = zl[(rb + 8 + g) * PZ + ko + tg];
            u32 al2 = zl[(rb + g) * PZ + ko + 4 + tg];
            u32 al3 = zl[(rb + 8 + g) * PZ + ko + 4 + tg];
#pragma unroll
            for (int j = 0; j < 4; j++) {
                int c0 = cb + j * 8 + g;
                u32 bh0 = W2h[(ko + tg) * PW + c0];
                u32 bh1 = W2h[(ko + 4 + tg) * PW + c0];
                u32 bl0 = W2l[(ko + tg) * PW + c0];
                u32 bl1 = W2l[(ko + 4 + tg) * PW + c0];
                mma16816(acc[j][0], acc[j][1], acc[j][2], acc[j][3],
                         ah0, ah1, ah2, ah3, bh0, bh1);
                mma16816(acc[j][0], acc[j][1], acc[j][2], acc[j][3],
                         ah0, ah1, ah2, ah3, bl0, bl1);
                mma16816(acc[j][0], acc[j][1], acc[j][2], acc[j][3],
                         al0, al1, al2, al3, bh0, bh1);
            }
        }

        // ---- out = relu(acc + b2) . Wd3 + bd3 ----
        {
            float pr0 = 0.f, pr1 = 0.f;
#pragma unroll
            for (int j = 0; j < 4; j++) {
                int col0 = cb + j * 8 + 2 * tg;
                float wa = w3s[col0], wb = w3s[col0 + 1];
                pr0 += fmaxf(acc[j][0] + b2s[col0],     0.f) * wa
                     + fmaxf(acc[j][1] + b2s[col0 + 1], 0.f) * wb;
                pr1 += fmaxf(acc[j][2] + b2s[col0],     0.f) * wa
                     + fmaxf(acc[j][3] + b2s[col0 + 1], 0.f) * wb;
            }
            // reduce over tg (quad)
            pr0 += __shfl_xor_sync(0xffffffffu, pr0, 1);
            pr0 += __shfl_xor_sync(0xffffffffu, pr0, 2);
            pr1 += __shfl_xor_sync(0xffffffffu, pr1, 1);
            pr1 += __shfl_xor_sync(0xffffffffu, pr1, 2);
            if (tg == 0) {
                red[(rb + g) * 4 + wc]     = pr0;
                red[(rb + 8 + g) * 4 + wc] = pr1;
            }
        }
        __syncthreads();

        if (tid < 64) {
            int p = tb + tid;
            if (p < total)
                out[p] = red[tid * 4] + red[tid * 4 + 1]
                       + red[tid * 4 + 2] + red[tid * 4 + 3] + b3;
        }
        __syncthreads();
    }
}

// ============================================================================
// launch — R10 two-stream structure
// ============================================================================
extern "C" void kernel_launch(void* const* d_in, const int* in_sizes, int n_in,
                              void* d_out, int out_size)
{
    const float* x    = (const float*)d_in[0];
    const int*   esrc = (const int*)  d_in[1];
    const int*   edst = (const int*)  d_in[2];
    const int*   ps   = (const int*)  d_in[3];
    const int*   pd   = (const int*)  d_in[4];
    const int*   ns   = (const int*)  d_in[5];
    const int*   nd   = (const int*)  d_in[6];
    const float* Ws1  = (const float*)d_in[7];
    const float* Wn1  = (const float*)d_in[8];
    const float* b1   = (const float*)d_in[9];
    const float* Ws2  = (const float*)d_in[10];
    const float* Wn2  = (const float*)d_in[11];
    const float* b2   = (const float*)d_in[12];
    const float* Wd1  = (const float*)d_in[13];
    const float* bd1  = (const float*)d_in[14];
    const float* Wd2  = (const float*)d_in[15];
    const float* bd2  = (const float*)d_in[16];
    const float* Wd3  = (const float*)d_in[17];
    const float* bd3  = (const float*)d_in[18];
    float* out = (float*)d_out;

    void *aggPtr, *h1Ptr, *h2Ptr;
    cudaGetSymbolAddress(&aggPtr, g_agg);
    cudaGetSymbolAddress(&h1Ptr,  g_h1);
    cudaGetSymbolAddress(&h2Ptr,  g_h2);
    float* h1 = (float*)h1Ptr;
    float* h2 = (float*)h2Ptr;
    float* agg = (float*)aggPtr;

    int nsm = 148;
    cudaDeviceGetAttribute(&nsm, cudaDevAttrMultiProcessorCount, 0);

    int rpb_sage = (((NN + nsm - 1) / nsm) + 7) & ~7;
    int rpb_dec  = (((2 * PP + nsm - 1) / nsm) + 63) & ~63;

    const int HALF_SMEM = 128 * 128 * 4 + 16 * 8 * 128 * 4;       // 131072 B
    const int DEC_SMEM  = DEC_U32 * 4;                            // ~176.6 KB
    cudaFuncSetAttribute(sage_half_kernel<false, false>,
                         cudaFuncAttributeMaxDynamicSharedMemorySize, HALF_SMEM);
    cudaFuncSetAttribute(sage_half_kernel<true, true>,
                         cudaFuncAttributeMaxDynamicSharedMemorySize, HALF_SMEM);
    cudaFuncSetAttribute(sage_half_kernel<true, false>,
                         cudaFuncAttributeMaxDynamicSharedMemorySize, HALF_SMEM);
    cudaFuncSetAttribute(decoder_kernel,
                         cudaFuncAttributeMaxDynamicSharedMemorySize, DEC_SMEM);

    static cudaStream_t sB = nullptr;
    static cudaEvent_t evFork = nullptr, evAgg1 = nullptr,
                       evH1 = nullptr, evAgg2 = nullptr;
    if (sB == nullptr) {
        cudaStreamCreateWithFlags(&sB, cudaStreamNonBlocking);
        cudaEventCreateWithFlags(&evFork, cudaEventDisableTiming);
        cudaEventCreateWithFlags(&evAgg1, cudaEventDisableTiming);
        cudaEventCreateWithFlags(&evH1,   cudaEventDisableTiming);
        cudaEventCreateWithFlags(&evAgg2, cudaEventDisableTiming);
    }

    int ablocks = (NN * 32 + 255) / 256;

    // ---- fork ----
    cudaEventRecord(evFork, 0);
    cudaStreamWaitEvent(sB, evFork, 0);

    // streamB: CSR build + aggregate layer 1
    count_kernel<<<(EE + 255) / 256, 256, 0, sB>>>(edst);
    scan_kernel<<<1, 1024, 0, sB>>>();
    fill_kernel<<<(EE + 255) / 256, 256, 0, sB>>>(esrc, edst);
    aggregate_kernel<<<ablocks, 256, 0, sB>>>(x);
    cudaEventRecord(evAgg1, sB);

    // streamA: self half of layer 1 (concurrent with CSR+agg1)
    sage_half_kernel<false, false><<<nsm, 512, HALF_SMEM>>>(x, Ws1, b1, h1,
                                                            rpb_sage);
    cudaStreamWaitEvent(0, evAgg1, 0);
    sage_half_kernel<true, true><<<nsm, 512, HALF_SMEM>>>(agg, Wn1, b1, h1,
                                                          rpb_sage);
    cudaEventRecord(evH1, 0);

    // streamB: aggregate layer 2 (concurrent with sage2_self)
    cudaStreamWaitEvent(sB, evH1, 0);
    aggregate_kernel<<<ablocks, 256, 0, sB>>>(h1);
    cudaEventRecord(evAgg2, sB);

    // streamA: self half of layer 2
    sage_half_kernel<false, false><<<nsm, 512, HALF_SMEM>>>(h1, Ws2, b2, h2,
                                                            rpb_sage);
    cudaStreamWaitEvent(0, evAgg2, 0);
    sage_half_kernel<true, false><<<nsm, 512, HALF_SMEM>>>(agg, Wn2, b2, h2,
                                                           rpb_sage);

    // decoder (mma.sync bf16 split)
    decoder_kernel<<<nsm, 512, DEC_SMEM>>>(h2, ps, pd, ns, nd,
                                           Wd1, bd1, Wd2, bd2, Wd3, bd3, out,
                                           rpb_dec);
}

// round 13
// speedup vs baseline: 1.3649x; 1.0262x over previous
#include <cuda_runtime.h>
#include <cuda_bf16.h>
#include <cstdint>

#define NN 50000
#define EE 600000
#define PP 100000
#define FD 128

// ---- device scratch ----
__device__ float g_agg[NN * FD];
__device__ float g_h1[NN * FD];
__device__ float g_h2[NN * FD];
__device__ int   g_cnt[NN];          // restored to 0 by fill_kernel each run
__device__ int   g_rowstart[NN + 1];
__device__ int   g_csr[EE];

typedef unsigned long long u64;
typedef unsigned int u32;

// bf16 split helpers
__device__ __forceinline__ void bf16_split(float x, unsigned short& h, unsigned short& l) {
    __nv_bfloat16 bh = __float2bfloat16(x);
    float r = x - __bfloat162float(bh);
    __nv_bfloat16 bl = __float2bfloat16(r);
    h = __bfloat16_as_ushort(bh);
    l = __bfloat16_as_ushort(bl);
}
__device__ __forceinline__ u32 pack16(unsigned short lo, unsigned short hi) {
    return (u32)lo | ((u32)hi << 16);
}

// m16n8k16 bf16 MMA, f32 accum
__device__ __forceinline__ void mma16816(float& c0, float& c1, float& c2, float& c3,
                                         u32 a0, u32 a1, u32 a2, u32 a3,
                                         u32 b0, u32 b1) {
    asm volatile(
        "mma.sync.aligned.m16n8k16.row.col.f32.bf16.bf16.f32 "
        "{%0,%1,%2,%3}, {%4,%5,%6,%7}, {%8,%9}, {%0,%1,%2,%3};"
        : "+f"(c0), "+f"(c1), "+f"(c2), "+f"(c3)
        : "r"(a0), "r"(a1), "r"(a2), "r"(a3), "r"(b0), "r"(b1));
}

// ============================================================================
// CSR build (proven)
// ============================================================================
__global__ void count_kernel(const int* __restrict__ dst)
{
    int e = blockIdx.x * blockDim.x + threadIdx.x;
    if (e < EE) atomicAdd(&g_cnt[dst[e]], 1);
}

__global__ void __launch_bounds__(1024, 1) scan_kernel()
{
    __shared__ int wsum[32];
    __shared__ int carry;
    int tid = threadIdx.x, lane = tid & 31, w = tid >> 5;
    if (tid == 0) carry = 0;
    __syncthreads();
    for (int base = 0; base < NN; base += 1024) {
        int i = base + tid;
        int v = (i < NN) ? g_cnt[i] : 0;
        int s = v;
#pragma unroll
        for (int off = 1; off < 32; off <<= 1) {
            int t = __shfl_up_sync(0xffffffffu, s, off);
            if (lane >= off) s += t;
        }
        if (lane == 31) wsum[w] = s;
        __syncthreads();
        if (w == 0) {
            int ws = wsum[lane];
#pragma unroll
            for (int off = 1; off < 32; off <<= 1) {
                int t = __shfl_up_sync(0xffffffffu, ws, off);
                if (lane >= off) ws += t;
            }
            wsum[lane] = ws;
        }
        __syncthreads();
        int prev = (w > 0) ? wsum[w - 1] : 0;
        int incl = carry + prev + s;
        if (i < NN) g_rowstart[i + 1] = incl;
        int chunk_total = wsum[31];
        __syncthreads();
        if (tid == 0) carry += chunk_total;
        __syncthreads();
    }
    if (threadIdx.x == 0) g_rowstart[0] = 0;
}

__global__ void fill_kernel(const int* __restrict__ src,
                            const int* __restrict__ dst)
{
    int e = blockIdx.x * blockDim.x + threadIdx.x;
    if (e >= EE) return;
    int d = dst[e];
    int p = atomicAdd(&g_cnt[d], -1) - 1;
    g_csr[g_rowstart[d] + p] = src[e];
}

// ============================================================================
// Aggregate (proven)
// ============================================================================
__global__ void aggregate_kernel(const float* __restrict__ h)
{
    int gw   = (blockIdx.x * blockDim.x + threadIdx.x) >> 5;
    int lane = threadIdx.x & 31;
    if (gw >= NN) return;
    int beg = g_rowstart[gw], end = g_rowstart[gw + 1];
    const float* hp = h + lane * 4;
    float4 acc = make_float4(0.f, 0.f, 0.f, 0.f);
    int e = beg;
    for (; e + 1 < end; e += 2) {
        int s0 = g_csr[e], s1 = g_csr[e + 1];
        float4 v0 = *(const float4*)(hp + s0 * FD);
        float4 v1 = *(const float4*)(hp + s1 * FD);
        acc.x += v0.x + v1.x; acc.y += v0.y + v1.y;
        acc.z += v0.z + v1.z; acc.w += v0.w + v1.w;
    }
    if (e < end) {
        int s0 = g_csr[e];
        float4 v0 = *(const float4*)(hp + s0 * FD);
        acc.x += v0.x; acc.y += v0.y; acc.z += v0.z; acc.w += v0.w;
    }
    float rd = 1.0f / fmaxf((float)(end - beg), 1.0f);
    acc.x *= rd; acc.y *= rd; acc.z *= rd; acc.w *= rd;
    *(float4*)(g_agg + gw * FD + lane * 4) = acc;
}

// ============================================================================
// Half-K SAGE linear via mma.sync bf16 3-term split (decoder recipe).
// Tile: 64 rows x 128 cols, K=128.
// 16 warps = 4 row-groups (16 rows) x 4 col-groups (32 cols).
// ADD=false: out = src @ W + b ; ADD=true: out += src @ W (then opt RELU)
// ============================================================================
#define SPW 136
#define SPZ 68
#define OFF_SWH 0
#define OFF_SWL (OFF_SWH + 64 * SPW)
#define OFF_SZH (OFF_SWL + 64 * SPW)
#define OFF_SZL (OFF_SZH + 64 * SPZ)
#define OFF_SB  (OFF_SZL + 64 * SPZ)
#define SAGE_U32 (OFF_SB + 128)

template <bool ADD, bool RELU>
__global__ void __launch_bounds__(512, 1)
sage_half_mma(const float* __restrict__ src,
              const float* __restrict__ W,
              const float* __restrict__ b,
              float* __restrict__ out,
              int rpb)
{
    extern __shared__ u32 smu[];
    u32* Wh = smu + OFF_SWH;
    u32* Wl = smu + OFF_SWL;
    u32* zh = smu + OFF_SZH;
    u32* zl = smu + OFF_SZL;
    float* bs = (float*)(smu + OFF_SB);

    int tid  = threadIdx.x;
    int lane = tid & 31;
    int warp = tid >> 5;
    int g    = lane >> 2;
    int tg   = lane & 3;
    int wr   = warp & 3;       // row-group
    int wc   = warp >> 2;      // col-group

    // ---- prologue: weight split (k-interleaved pairs) ----
    for (int i = tid; i < 64 * 128; i += 512) {
        int t = i >> 7, c = i & 127;
        unsigned short h0, l0, h1, l1;
        bf16_split(W[(2 * t) * 128 + c], h0, l0);
        bf16_split(W[(2 * t + 1) * 128 + c], h1, l1);
        Wh[t * SPW + c] = pack16(h0, h1);
        Wl[t * SPW + c] = pack16(l0, l1);
    }
    if (tid < 128) bs[tid] = b[tid];
    __syncthreads();

    int bstart = blockIdx.x * rpb;
    int bend   = min(bstart + rpb, NN);
    int rb = wr * 16;
    int cb = wc * 32;

    for (int tb = bstart; tb < bend; tb += 64) {

        // ---- stage 64 rows, split to bf16 hi/lo pairs ----
#pragma unroll
        for (int i = 0; i < 4; i++) {
            int rl  = warp * 4 + i;
            int row = tb + rl;
            float4 v = make_float4(0.f, 0.f, 0.f, 0.f);
            if (row < bend)
                v = *(const float4*)(src + row * FD + lane * 4);
            unsigned short h0, l0, h1, l1, h2_, l2_, h3_, l3_;
            bf16_split(v.x, h0, l0); bf16_split(v.y, h1, l1);
            bf16_split(v.z, h2_, l2_); bf16_split(v.w, h3_, l3_);
            u32 base_ = rl * SPZ + 2 * lane;
            *(uint2*)(zh + base_) = make_uint2(pack16(h0, h1), pack16(h2_, h3_));
            *(uint2*)(zl + base_) = make_uint2(pack16(l0, l1), pack16(l2_, l3_));
        }
        __syncthreads();

        float acc[4][4];
#pragma unroll
        for (int j = 0; j < 4; j++)
#pragma unroll
            for (int q = 0; q < 4; q++) acc[j][q] = 0.f;

#pragma unroll 1
        for (int ks = 0; ks < 8; ks++) {
            int ko = ks * 8;
            u32 ah0 = zh[(rb + g) * SPZ + ko + tg];
            u32 ah1 = zh[(rb + 8 + g) * SPZ + ko + tg];
            u32 ah2 = zh[(rb + g) * SPZ + ko + 4 + tg];
            u32 ah3 = zh[(rb + 8 + g) * SPZ + ko + 4 + tg];
            u32 al0 = zl[(rb + g) * SPZ + ko + tg];
            u32 al1 = zl[(rb + 8 + g) * SPZ + ko + tg];
            u32 al2 = zl[(rb + g) * SPZ + ko + 4 + tg];
            u32 al3 = zl[(rb + 8 + g) * SPZ + ko + 4 + tg];
#pragma unroll
            for (int j = 0; j < 4; j++) {
                int c0 = cb + j * 8 + g;
                u32 bh0 = Wh[(ko + tg) * SPW + c0];
                u32 bh1 = Wh[(ko + 4 + tg) * SPW + c0];
                u32 bl0 = Wl[(ko + tg) * SPW + c0];
                u32 bl1 = Wl[(ko + 4 + tg) * SPW + c0];
                mma16816(acc[j][0], acc[j][1], acc[j][2], acc[j][3],
                         ah0, ah1, ah2, ah3, bh0, bh1);
                mma16816(acc[j][0], acc[j][1], acc[j][2], acc[j][3],
                         ah0, ah1, ah2, ah3, bl0, bl1);
                mma16816(acc[j][0], acc[j][1], acc[j][2], acc[j][3],
                         al0, al1, al2, al3, bh0, bh1);
            }
        }

        // ---- epilogue: write 16x32 per warp ----
        {
            int r0 = tb + rb + g;
            int r1 = tb + rb + 8 + g;
#pragma unroll
            for (int j = 0; j < 4; j++) {
                int col0 = cb + j * 8 + 2 * tg;
                float2 bb = make_float2(0.f, 0.f);
                if (!ADD) bb = *(float2*)(bs + col0);
                if (r0 < bend) {
                    float2* op = (float2*)(out + r0 * FD + col0);
                    float2 o;
                    if (ADD) {
                        float2 prev = *op;
                        o.x = acc[j][0] + prev.x;
                        o.y = acc[j][1] + prev.y;
                    } else {
                        o.x = acc[j][0] + bb.x;
                        o.y = acc[j][1] + bb.y;
                    }
                    if (RELU) { o.x = fmaxf(o.x, 0.f); o.y = fmaxf(o.y, 0.f); }
                    *op = o;
                }
                if (r1 < bend) {
                    float2* op = (float2*)(out + r1 * FD + col0);
                    float2 o;
                    if (ADD) {
                        float2 prev = *op;
                        o.x = acc[j][2] + prev.x;
                        o.y = acc[j][3] + prev.y;
                    } else {
                        o.x = acc[j][2] + bb.x;
                        o.y = acc[j][3] + bb.y;
                    }
                    if (RELU) { o.x = fmaxf(o.x, 0.f); o.y = fmaxf(o.y, 0.f); }
                    *op = o;
                }
            }
        }
        __syncthreads();
    }
}

// ============================================================================
// Decoder via mma.sync (R12 form, FROZEN)
// ============================================================================
#define PW 136
#define PZ 68
#define OFF_W1H 0
#define OFF_W1L (OFF_W1H + 64 * PW)
#define OFF_W2H (OFF_W1L + 64 * PW)
#define OFF_W2L (OFF_W2H + 64 * PW)
#define OFF_ZH  (OFF_W2L + 64 * PW)
#define OFF_ZL  (OFF_ZH + 64 * PZ)
#define OFF_B1  (OFF_ZL + 64 * PZ)
#define OFF_B2  (OFF_B1 + 128)
#define OFF_W3  (OFF_B2 + 128)
#define OFF_RED (OFF_W3 + 128)
#define DEC_U32 (OFF_RED + 64 * 4)

__global__ void __launch_bounds__(512, 1)
decoder_kernel(const float* __restrict__ h,
               const int* __restrict__ ps, const int* __restrict__ pd,
               const int* __restrict__ ns, const int* __restrict__ nd,
               const float* __restrict__ Wd1, const float* __restrict__ bd1,
               const float* __restrict__ Wd2, const float* __restrict__ bd2,
               const float* __restrict__ Wd3, const float* __restrict__ bd3,
               float* __restrict__ out,
               int rpb)
{
    extern __shared__ u32 smu[];
    u32* W1h = smu + OFF_W1H;
    u32* W1l = smu + OFF_W1L;
    u32* W2h = smu + OFF_W2H;
    u32* W2l = smu + OFF_W2L;
    u32* zh  = smu + OFF_ZH;
    u32* zl  = smu + OFF_ZL;
    float* b1s = (float*)(smu + OFF_B1);
    float* b2s = (float*)(smu + OFF_B2);
    float* w3s = (float*)(smu + OFF_W3);
    float* red = (float*)(smu + OFF_RED);

    int tid  = threadIdx.x;
    int lane = tid & 31;
    int warp = tid >> 5;
    int g    = lane >> 2;
    int tg   = lane & 3;
    int wr   = warp & 3;
    int wc   = warp >> 2;

    for (int i = tid; i < 64 * 128; i += 512) {
        int t = i >> 7, c = i & 127;
        unsigned short h0, l0, h1, l1;
        float a0 = Wd1[(2 * t) * 128 + c], a1 = Wd1[(2 * t + 1) * 128 + c];
        bf16_split(a0, h0, l0); bf16_split(a1, h1, l1);
        W1h[t * PW + c] = pack16(h0, h1);
        W1l[t * PW + c] = pack16(l0, l1);
        float b0f = Wd2[(2 * t) * 128 + c], b1f = Wd2[(2 * t + 1) * 128 + c];
        bf16_split(b0f, h0, l0); bf16_split(b1f, h1, l1);
        W2h[t * PW + c] = pack16(h0, h1);
        W2l[t * PW + c] = pack16(l0, l1);
    }
    if (tid < 128) {
        b1s[tid] = bd1[tid];
        b2s[tid] = bd2[tid];
        w3s[tid] = Wd3[tid];
    }
    __syncthreads();

    const float b3 = bd3[0];
    const int total = 2 * PP;
    int bstart = blockIdx.x * rpb;
    int bend   = min(bstart + rpb, total);

    for (int tb = bstart; tb < bend; tb += 64) {

        {
#pragma unroll
            for (int i = 0; i < 4; i++) {
                int rl = warp * 4 + i;
                int p  = tb + rl;
                float4 v = make_float4(0.f, 0.f, 0.f, 0.f);
                if (p < total) {
                    int s, d;
                    if (p < PP) { s = ps[p]; d = pd[p]; }
                    else        { s = ns[p - PP]; d = nd[p - PP]; }
                    float4 a = *(const float4*)(h + s * FD + lane * 4);
                    float4 c = *(const float4*)(h + d * FD + lane * 4);
                    v.x = a.x * c.x; v.y = a.y * c.y;
                    v.z = a.z * c.z; v.w = a.w * c.w;
                }
                unsigned short h0, l0, h1, l1, h2_, l2_, h3_, l3_;
                bf16_split(v.x, h0, l0); bf16_split(v.y, h1, l1);
                bf16_split(v.z, h2_, l2_); bf16_split(v.w, h3_, l3_);
                u32 base_ = rl * PZ + 2 * lane;
                *(uint2*)(zh + base_) = make_uint2(pack16(h0, h1), pack16(h2_, h3_));
                *(uint2*)(zl + base_) = make_uint2(pack16(l0, l1), pack16(l2_, l3_));
            }
        }
        __syncthreads();

        float acc[4][4];
        int rb = wr * 16;
        int cb = wc * 32;

        // ---- GEMV 1 ----
#pragma unroll
        for (int j = 0; j < 4; j++)
#pragma unroll
            for (int q = 0; q < 4; q++) acc[j][q] = 0.f;

#pragma unroll 1
        for (int ks = 0; ks < 8; ks++) {
            int ko = ks * 8;
            u32 ah0 = zh[(rb + g) * PZ + ko + tg];
            u32 ah1 = zh[(rb + 8 + g) * PZ + ko + tg];
            u32 ah2 = zh[(rb + g) * PZ + ko + 4 + tg];
            u32 ah3 = zh[(rb + 8 + g) * PZ + ko + 4 + tg];
            u32 al0 = zl[(rb + g) * PZ + ko + tg];
            u32 al1 = zl[(rb + 8 + g) * PZ + ko + tg];
            u32 al2 = zl[(rb + g) * PZ + ko + 4 + tg];
            u32 al3 = zl[(rb + 8 + g) * PZ + ko + 4 + tg];
#pragma unroll
            for (int j = 0; j < 4; j++) {
                int c0 = cb + j * 8 + g;
                u32 bh0 = W1h[(ko + tg) * PW + c0];
                u32 bh1 = W1h[(ko + 4 + tg) * PW + c0];
                u32 bl0 = W1l[(ko + tg) * PW + c0];
                u32 bl1 = W1l[(ko + 4 + tg) * PW + c0];
                mma16816(acc[j][0], acc[j][1], acc[j][2], acc[j][3],
                         ah0, ah1, ah2, ah3, bh0, bh1);
                mma16816(acc[j][0], acc[j][1], acc[j][2], acc[j][3],
                         ah0, ah1, ah2, ah3, bl0, bl1);
                mma16816(acc[j][0], acc[j][1], acc[j][2], acc[j][3],
                         al0, al1, al2, al3, bh0, bh1);
            }
        }
        __syncthreads();

        // ---- t1 = relu(acc + b1), restage ----
#pragma unroll
        for (int j = 0; j < 4; j++) {
            int col0 = cb + j * 8 + 2 * tg;
            float t0 = fmaxf(acc[j][0] + b1s[col0],     0.f);
            float t1 = fmaxf(acc[j][1] + b1s[col0 + 1], 0.f);
            float t2 = fmaxf(acc[j][2] + b1s[col0],     0.f);
            float t3 = fmaxf(acc[j][3] + b1s[col0 + 1], 0.f);
            unsigned short h0, l0, h1, l1;
            int t2i = col0 >> 1;
            bf16_split(t0, h0, l0); bf16_split(t1, h1, l1);
            zh[(rb + g) * PZ + t2i] = pack16(h0, h1);
            zl[(rb + g) * PZ + t2i] = pack16(l0, l1);
            bf16_split(t2, h0, l0); bf16_split(t3, h1, l1);
            zh[(rb + 8 + g) * PZ + t2i] = pack16(h0, h1);
            zl[(rb + 8 + g) * PZ + t2i] = pack16(l0, l1);
        }
        __syncthreads();

        // ---- GEMV 2 ----
#pragma unroll
        for (int j = 0; j < 4; j++)
#pragma unroll
            for (int q = 0; q < 4; q++) acc[j][q] = 0.f;

#pragma unroll 1
        for (int ks = 0; ks < 8; ks++) {
            int ko = ks * 8;
            u32 ah0 = zh[(rb + g) * PZ + ko + tg];
            u32 ah1 = zh[(rb + 8 + g) * PZ + ko + tg];
            u32 ah2 = zh[(rb + g) * PZ + ko + 4 + tg];
            u32 ah3 = zh[(rb + 8 + g) * PZ + ko + 4 + tg];
            u32 al0 = zl[(rb + g) * PZ + ko + tg];
            u32 al1 = zl[(rb + 8 + g) * PZ + ko + tg];
            u32 al2 = zl[(rb + g) * PZ + ko + 4 + tg];
            u32 al3 = zl[(rb + 8 + g) * PZ + ko + 4 + tg];
#pragma unroll
            for (int j = 0; j < 4; j++) {
                int c0 = cb + j * 8 + g;
                u32 bh0 = W2h[(ko + tg) * PW + c0];
                u32 bh1 = W2h[(ko + 4 + tg) * PW + c0];
                u32 bl0 = W2l[(ko + tg) * PW + c0];
                u32 bl1 = W2l[(ko + 4 + tg) * PW + c0];
                mma16816(acc[j][0], acc[j][1], acc[j][2], acc[j][3],
                         ah0, ah1, ah2, ah3, bh0, bh1);
                mma16816(acc[j][0], acc[j][1], acc[j][2], acc[j][3],
                         ah0, ah1, ah2, ah3, bl0, bl1);
                mma16816(acc[j][0], acc[j][1], acc[j][2], acc[j][3],
                         al0, al1, al2, al3, bh0, bh1);
            }
        }

        // ---- out = relu(acc + b2) . Wd3 + bd3 ----
        {
            float pr0 = 0.f, pr1 = 0.f;
#pragma unroll
            for (int j = 0; j < 4; j++) {
                int col0 = cb + j * 8 + 2 * tg;
                float wa = w3s[col0], wb = w3s[col0 + 1];
                pr0 += fmaxf(acc[j][0] + b2s[col0],     0.f) * wa
                     + fmaxf(acc[j][1] + b2s[col0 + 1], 0.f) * wb;
                pr1 += fmaxf(acc[j][2] + b2s[col0],     0.f) * wa
                     + fmaxf(acc[j][3] + b2s[col0 + 1], 0.f) * wb;
            }
            pr0 += __shfl_xor_sync(0xffffffffu, pr0, 1);
            pr0 += __shfl_xor_sync(0xffffffffu, pr0, 2);
            pr1 += __shfl_xor_sync(0xffffffffu, pr1, 1);
            pr1 += __shfl_xor_sync(0xffffffffu, pr1, 2);
            if (tg == 0) {
                red[(rb + g) * 4 + wc]     = pr0;
                red[(rb + 8 + g) * 4 + wc] = pr1;
            }
        }
        __syncthreads();

        if (tid < 64) {
            int p = tb + tid;
            if (p < total)
                out[p] = red[tid * 4] + red[tid * 4 + 1]
                       + red[tid * 4 + 2] + red[tid * 4 + 3] + b3;
        }
        __syncthreads();
    }
}

// ============================================================================
// launch — two-stream fork/join
// ============================================================================
extern "C" void kernel_launch(void* const* d_in, const int* in_sizes, int n_in,
                              void* d_out, int out_size)
{
    const float* x    = (const float*)d_in[0];
    const int*   esrc = (const int*)  d_in[1];
    const int*   edst = (const int*)  d_in[2];
    const int*   ps   = (const int*)  d_in[3];
    const int*   pd   = (const int*)  d_in[4];
    const int*   ns   = (const int*)  d_in[5];
    const int*   nd   = (const int*)  d_in[6];
    const float* Ws1  = (const float*)d_in[7];
    const float* Wn1  = (const float*)d_in[8];
    const float* b1   = (const float*)d_in[9];
    const float* Ws2  = (const float*)d_in[10];
    const float* Wn2  = (const float*)d_in[11];
    const float* b2   = (const float*)d_in[12];
    const float* Wd1  = (const float*)d_in[13];
    const float* bd1  = (const float*)d_in[14];
    const float* Wd2  = (const float*)d_in[15];
    const float* bd2  = (const float*)d_in[16];
    const float* Wd3  = (const float*)d_in[17];
    const float* bd3  = (const float*)d_in[18];
    float* out = (float*)d_out;

    void *aggPtr, *h1Ptr, *h2Ptr;
    cudaGetSymbolAddress(&aggPtr, g_agg);
    cudaGetSymbolAddress(&h1Ptr,  g_h1);
    cudaGetSymbolAddress(&h2Ptr,  g_h2);
    float* h1 = (float*)h1Ptr;
    float* h2 = (float*)h2Ptr;
    float* agg = (float*)aggPtr;

    int nsm = 148;
    cudaDeviceGetAttribute(&nsm, cudaDevAttrMultiProcessorCount, 0);

    int rpb_sage = (((NN + nsm - 1) / nsm) + 7) & ~7;
    int rpb_dec  = (((2 * PP + nsm - 1) / nsm) + 63) & ~63;

    const int SAGE_SMEM = SAGE_U32 * 4;    // ~105 KB
    const int DEC_SMEM  = DEC_U32 * 4;     // ~177 KB
    cudaFuncSetAttribute(sage_half_mma<false, false>,
                         cudaFuncAttributeMaxDynamicSharedMemorySize, SAGE_SMEM);
    cudaFuncSetAttribute(sage_half_mma<true, true>,
                         cudaFuncAttributeMaxDynamicSharedMemorySize, SAGE_SMEM);
    cudaFuncSetAttribute(sage_half_mma<true, false>,
                         cudaFuncAttributeMaxDynamicSharedMemorySize, SAGE_SMEM);
    cudaFuncSetAttribute(decoder_kernel,
                         cudaFuncAttributeMaxDynamicSharedMemorySize, DEC_SMEM);

    static cudaStream_t sB = nullptr;
    static cudaEvent_t evFork = nullptr, evAgg1 = nullptr,
                       evH1 = nullptr, evAgg2 = nullptr;
    if (sB == nullptr) {
        cudaStreamCreateWithFlags(&sB, cudaStreamNonBlocking);
        cudaEventCreateWithFlags(&evFork, cudaEventDisableTiming);
        cudaEventCreateWithFlags(&evAgg1, cudaEventDisableTiming);
        cudaEventCreateWithFlags(&evH1,   cudaEventDisableTiming);
        cudaEventCreateWithFlags(&evAgg2, cudaEventDisableTiming);
    }

    int ablocks = (NN * 32 + 255) / 256;

    // ---- fork ----
    cudaEventRecord(evFork, 0);
    cudaStreamWaitEvent(sB, evFork, 0);

    // streamB: CSR build + aggregate layer 1
    count_kernel<<<(EE + 255) / 256, 256, 0, sB>>>(edst);
    scan_kernel<<<1, 1024, 0, sB>>>();
    fill_kernel<<<(EE + 255) / 256, 256, 0, sB>>>(esrc, edst);
    aggregate_kernel<<<ablocks, 256, 0, sB>>>(x);
    cudaEventRecord(evAgg1, sB);

    // streamA: self half of layer 1 (concurrent with CSR+agg1)
    sage_half_mma<false, false><<<nsm, 512, SAGE_SMEM>>>(x, Ws1, b1, h1,
                                                         rpb_sage);
    cudaStreamWaitEvent(0, evAgg1, 0);
    sage_half_mma<true, true><<<nsm, 512, SAGE_SMEM>>>(agg, Wn1, b1, h1,
                                                       rpb_sage);
    cudaEventRecord(evH1, 0);

    // streamB: aggregate layer 2 (concurrent with sage2_self)
    cudaStreamWaitEvent(sB, evH1, 0);
    aggregate_kernel<<<ablocks, 256, 0, sB>>>(h1);
    cudaEventRecord(evAgg2, sB);

    // streamA: self half of layer 2
    sage_half_mma<false, false><<<nsm, 512, SAGE_SMEM>>>(h1, Ws2, b2, h2,
                                                         rpb_sage);
    cudaStreamWaitEvent(0, evAgg2, 0);
    sage_half_mma<true, false><<<nsm, 512, SAGE_SMEM>>>(agg, Wn2, b2, h2,
                                                        rpb_sage);

    // decoder
    decoder_kernel<<<nsm, 512, DEC_SMEM>>>(h2, ps, pd, ns, nd,
                                           Wd1, bd1, Wd2, bd2, Wd3, bd3, out,
                                           rpb_dec);
}